// round 2
// baseline (speedup 1.0000x reference)
#include <cuda_runtime.h>
#include <cuda_bf16.h>
#include <cstdint>

// ---------------- problem constants ----------------
#define NGRAPH 8192
#define NPG    39
#define EPG    312            // NPG * 8
#define NTOT   (NGRAPH * NPG) // 319488
#define ETOT   (NGRAPH * EPG) // 2555904
#define FDIM   4560
#define NEG_SLOPE 0.2f

// feature-row layout offsets
#define OFF_RES0 0
#define OFF_RES1 39
#define OFF_RES2 351
#define OFF_RES3 2847
#define OFF_RES4 4095
#define OFF_OUT0 4446
#define OFF_OUT1 4447
#define OFF_OUT2 4455
#define OFF_OUT3 4519
#define OFF_OUT4 4551

// ---------------- scratch (device globals; no allocation allowed) ----------
__device__ float g_feat[(size_t)NGRAPH * FDIM];   // 149.4 MB
__device__ float g_m1[(size_t)NGRAPH * 1024];     // 33.5 MB
__device__ float g_m2[(size_t)NGRAPH * 128];      // 4.2 MB

// ---------------- helpers ----------------
__device__ __forceinline__ float lrelu(float v) {
    return v >= 0.f ? v : NEG_SLOPE * v;
}
// monotone float->uint encoding for atomicMax
__device__ __forceinline__ unsigned encf(float f) {
    unsigned u = __float_as_uint(f);
    return (u & 0x80000000u) ? ~u : (u | 0x80000000u);
}
__device__ __forceinline__ float decf(unsigned u) {
    u = (u & 0x80000000u) ? (u & 0x7fffffffu) : ~u;
    return __uint_as_float(u);
}

// packed f32x2 FMA (2x FFMA rate vs 3-reg FFMA on sm_103a; PTX-only path)
__device__ __forceinline__ unsigned long long pk2(float x, float y) {
    unsigned long long u;
    asm("mov.b64 %0, {%1, %2};" : "=l"(u) : "f"(x), "f"(y));
    return u;
}
__device__ __forceinline__ void upk2(unsigned long long u, float& x, float& y) {
    asm("mov.b64 {%0, %1}, %2;" : "=f"(x), "=f"(y) : "l"(u));
}
__device__ __forceinline__ void ffma2(unsigned long long& c, unsigned long long a,
                                      unsigned long long b) {
    asm("fma.rn.f32x2 %0, %1, %2, %0;" : "+l"(c) : "l"(a), "l"(b));
}

// ---------------- GAT kernel: one CTA per graph ----------------
template <int Fi, int Fo>
__device__ void gat_layer_dev(
    float* __restrict__ xin, float* __restrict__ h, float* __restrict__ Wsh,
    float* __restrict__ sas, float* __restrict__ sad, float* __restrict__ sb,
    float* __restrict__ ss, float* __restrict__ sd, float* __restrict__ sden,
    unsigned* __restrict__ sm, float* __restrict__ sw,
    const short* __restrict__ es, const short* __restrict__ ed,
    const float* __restrict__ W, const float* __restrict__ a_s,
    const float* __restrict__ a_d, const float* __restrict__ bias,
    float* __restrict__ frow, int res_off, int pool_off)
{
    const int tid = threadIdx.x;
    // stage weights
    for (int i = tid; i < Fi * Fo; i += 256) Wsh[i] = W[i];
    if (tid < Fo) { sas[tid] = a_s[tid]; sad[tid] = a_d[tid]; sb[tid] = bias[tid]; }
    __syncthreads();

    // h = xin @ W
    for (int idx = tid; idx < NPG * Fo; idx += 256) {
        int n = idx / Fo, f = idx - n * Fo;
        float acc = 0.f;
        #pragma unroll
        for (int i = 0; i < Fi; i++) acc += xin[n * Fi + i] * Wsh[i * Fo + f];
        h[idx] = acc;
    }
    __syncthreads();

    // s, d, self-loop max seed, denom init; zero output accumulator (reuse xin)
    if (tid < NPG) {
        float a = 0.f, b = 0.f;
        #pragma unroll
        for (int f = 0; f < Fo; f++) {
            float hv = h[tid * Fo + f];
            a += hv * sas[f];
            b += hv * sad[f];
        }
        ss[tid] = a;
        sd[tid] = b;
        sm[tid] = encf(lrelu(a + b));
        sden[tid] = 0.f;
    }
    for (int idx = tid; idx < NPG * Fo; idx += 256) xin[idx] = 0.f;
    __syncthreads();

    // pass 1: per-dst max over edges (self already seeded)
    for (int e = tid; e < EPG; e += 256) {
        float v = lrelu(ss[es[e]] + sd[ed[e]]);
        sw[e] = v;
        atomicMax(&sm[ed[e]], encf(v));
    }
    __syncthreads();

    // pass 2a: softmax weights + denom
    if (tid < NPG) {
        float m = decf(sm[tid]);
        float wself = expf(lrelu(ss[tid] + sd[tid]) - m);
        atomicAdd(&sden[tid], wself);
        ss[tid] = wself;  // reuse ss as self-weight
    }
    for (int e = tid; e < EPG; e += 256) {
        float w = expf(sw[e] - decf(sm[ed[e]]));
        sw[e] = w;
        atomicAdd(&sden[ed[e]], w);
    }
    __syncthreads();

    // pass 2b: weighted aggregation into xin (output accumulator)
    for (int idx = tid; idx < EPG * Fo; idx += 256) {
        int e = idx / Fo, f = idx - e * Fo;
        atomicAdd(&xin[ed[e] * Fo + f], sw[e] * h[es[e] * Fo + f]);
    }
    for (int idx = tid; idx < NPG * Fo; idx += 256) {
        int n = idx / Fo;
        atomicAdd(&xin[idx], ss[n] * h[idx]);
    }
    __syncthreads();

    // finalize: normalize, bias, relu; write res slice
    for (int idx = tid; idx < NPG * Fo; idx += 256) {
        int n = idx / Fo, f = idx - n * Fo;
        float o = xin[idx] / (sden[n] + 1e-16f) + sb[f];
        o = fmaxf(o, 0.f);
        xin[idx] = o;
        frow[res_off + idx] = o;
    }
    __syncthreads();

    // pool: per-feature max over nodes
    for (int f = tid; f < Fo; f += 256) {
        float mx = -3.4e38f;
        #pragma unroll 1
        for (int n = 0; n < NPG; n++) mx = fmaxf(mx, xin[n * Fo + f]);
        frow[pool_off + f] = mx;
    }
    __syncthreads();
}

__global__ void __launch_bounds__(256)
gat_kernel(const float* __restrict__ x, const int* __restrict__ ei,
           const float* __restrict__ W1, const float* __restrict__ as1,
           const float* __restrict__ ad1, const float* __restrict__ b1,
           const float* __restrict__ W2, const float* __restrict__ as2,
           const float* __restrict__ ad2, const float* __restrict__ b2,
           const float* __restrict__ W3, const float* __restrict__ as3,
           const float* __restrict__ ad3, const float* __restrict__ b3,
           const float* __restrict__ W4, const float* __restrict__ as4,
           const float* __restrict__ ad4, const float* __restrict__ b4,
           float* __restrict__ feat)
{
    __shared__ float s_xin[NPG * 64];
    __shared__ float s_h[NPG * 64];
    __shared__ float s_W[64 * 32];
    __shared__ float s_as[64], s_ad[64], s_b[64];
    __shared__ float s_s[NPG], s_d[NPG], s_den[NPG];
    __shared__ unsigned s_m[NPG];
    __shared__ float s_w[EPG];
    __shared__ short s_es[EPG], s_ed[EPG];

    const int g = blockIdx.x;
    const int tid = threadIdx.x;
    float* frow = g_feat + (size_t)g * FDIM;

    const int ebase = g * EPG;
    const int nbase = g * NPG;
    for (int e = tid; e < EPG; e += 256) {
        s_es[e] = (short)(ei[ebase + e] - nbase);
        s_ed[e] = (short)(ei[ETOT + ebase + e] - nbase);
    }
    if (tid < NPG) {
        float xv = x[nbase + tid];
        s_xin[tid] = xv;
        frow[OFF_RES0 + tid] = xv;
    }
    __syncthreads();
    if (tid == 0) {
        float mx = -3.4e38f;
        for (int n = 0; n < NPG; n++) mx = fmaxf(mx, s_xin[n]);
        frow[OFF_OUT0] = mx;
    }

    gat_layer_dev<1, 8>(s_xin, s_h, s_W, s_as, s_ad, s_b, s_s, s_d, s_den, s_m,
                        s_w, s_es, s_ed, W1, as1, ad1, b1, frow, OFF_RES1, OFF_OUT1);
    gat_layer_dev<8, 64>(s_xin, s_h, s_W, s_as, s_ad, s_b, s_s, s_d, s_den, s_m,
                         s_w, s_es, s_ed, W2, as2, ad2, b2, frow, OFF_RES2, OFF_OUT2);
    gat_layer_dev<64, 32>(s_xin, s_h, s_W, s_as, s_ad, s_b, s_s, s_d, s_den, s_m,
                          s_w, s_es, s_ed, W3, as3, ad3, b3, frow, OFF_RES3, OFF_OUT3);
    gat_layer_dev<32, 9>(s_xin, s_h, s_W, s_as, s_ad, s_b, s_s, s_d, s_den, s_m,
                         s_w, s_es, s_ed, W4, as4, ad4, b4, frow, OFF_RES4, OFF_OUT4);
}

// ---------------- GEMM (+bias, optional relu), f32x2-packed FMAs -----------
template <int BM, int BN, int BK, int TM, int TN, bool RELU>
__global__ void __launch_bounds__((BM / TM) * (BN / TN))
gemm_bias_act(const float* __restrict__ A, const float* __restrict__ Bm,
              const float* __restrict__ bias, float* __restrict__ C,
              int M, int N, int K)
{
    constexpr int THREADS = (BM / TM) * (BN / TN);
    constexpr int NT = BN / TN;
    __shared__ float As[BK][BM];
    __shared__ float Bs[BK][BN];
    const int tid = threadIdx.x;
    const int row0 = blockIdx.y * BM;
    const int col0 = blockIdx.x * BN;
    const int tr = tid / NT;
    const int tc = tid % NT;

    unsigned long long acc[TM][TN / 2];
    #pragma unroll
    for (int i = 0; i < TM; i++)
        #pragma unroll
        for (int j = 0; j < TN / 2; j++) acc[i][j] = 0ull;

    constexpr int AV = BM * BK / (4 * THREADS);
    constexpr int BV = BK * BN / (4 * THREADS);

    for (int k0 = 0; k0 < K; k0 += BK) {
        #pragma unroll
        for (int v = 0; v < AV; v++) {
            int e = (tid + v * THREADS) * 4;
            int r = e / BK, kk = e % BK;
            float4 t = *(const float4*)(A + (size_t)(row0 + r) * K + (k0 + kk));
            As[kk + 0][r] = t.x; As[kk + 1][r] = t.y;
            As[kk + 2][r] = t.z; As[kk + 3][r] = t.w;
        }
        #pragma unroll
        for (int v = 0; v < BV; v++) {
            int e = (tid + v * THREADS) * 4;
            int kk = e / BN, c = e % BN;
            *(float4*)&Bs[kk][c] = *(const float4*)(Bm + (size_t)(k0 + kk) * N + (col0 + c));
        }
        __syncthreads();

        #pragma unroll
        for (int kk = 0; kk < BK; kk++) {
            float a[TM], b[TN];
            if constexpr (TM == 8) {
                float4 a0 = *(const float4*)&As[kk][tr * 4];
                float4 a1 = *(const float4*)&As[kk][BM / 2 + tr * 4];
                a[0] = a0.x; a[1] = a0.y; a[2] = a0.z; a[3] = a0.w;
                a[4] = a1.x; a[5] = a1.y; a[6] = a1.z; a[7] = a1.w;
            } else {
                float4 a0 = *(const float4*)&As[kk][tr * 4];
                a[0] = a0.x; a[1] = a0.y; a[2] = a0.z; a[3] = a0.w;
            }
            if constexpr (TN == 8) {
                float4 b0 = *(const float4*)&Bs[kk][tc * 4];
                float4 b1 = *(const float4*)&Bs[kk][BN / 2 + tc * 4];
                b[0] = b0.x; b[1] = b0.y; b[2] = b0.z; b[3] = b0.w;
                b[4] = b1.x; b[5] = b1.y; b[6] = b1.z; b[7] = b1.w;
            } else {
                float4 b0 = *(const float4*)&Bs[kk][tc * 4];
                b[0] = b0.x; b[1] = b0.y; b[2] = b0.z; b[3] = b0.w;
            }
            unsigned long long bb[TN / 2];
            #pragma unroll
            for (int j = 0; j < TN / 2; j++) bb[j] = pk2(b[2 * j], b[2 * j + 1]);
            #pragma unroll
            for (int i = 0; i < TM; i++) {
                unsigned long long ai = pk2(a[i], a[i]);
                #pragma unroll
                for (int j = 0; j < TN / 2; j++) ffma2(acc[i][j], ai, bb[j]);
            }
        }
        __syncthreads();
    }

    // epilogue
    #pragma unroll
    for (int i = 0; i < TM; i++) {
        int row;
        if constexpr (TM == 8)
            row = (i < 4) ? (tr * 4 + i) : (BM / 2 + tr * 4 + i - 4);
        else
            row = tr * 4 + i;
        row += row0;
        #pragma unroll
        for (int j = 0; j < TN / 2; j++) {
            float v0, v1;
            upk2(acc[i][j], v0, v1);
            int cb = 2 * j;
            int col;
            if constexpr (TN == 8)
                col = (cb < 4) ? (tc * 4 + cb) : (BN / 2 + tc * 4 + cb - 4);
            else
                col = tc * 4 + cb;
            col += col0;
            v0 += bias[col];
            v1 += bias[col + 1];
            if (RELU) { v0 = fmaxf(v0, 0.f); v1 = fmaxf(v1, 0.f); }
            C[(size_t)row * N + col] = v0;
            C[(size_t)row * N + col + 1] = v1;
        }
    }
}

// ---------------- final tiny GEMM: [8192,128] @ [128,9] + b ----------------
__global__ void gemm3_kernel(const float* __restrict__ A, const float* __restrict__ W,
                             const float* __restrict__ bias, float* __restrict__ C)
{
    int idx = blockIdx.x * blockDim.x + threadIdx.x;
    if (idx >= NGRAPH * 9) return;
    int m = idx / 9, n = idx - m * 9;
    const float* a = A + (size_t)m * 128;
    float acc = 0.f;
    #pragma unroll 8
    for (int k = 0; k < 128; k++) acc += a[k] * W[k * 9 + n];
    C[idx] = acc + bias[n];
}

// ---------------- launch ----------------
extern "C" void kernel_launch(void* const* d_in, const int* in_sizes, int n_in,
                              void* d_out, int out_size)
{
    (void)in_sizes; (void)n_in; (void)out_size;
    const float* x   = (const float*)d_in[0];
    const int*   ei  = (const int*)d_in[1];
    // d_in[2] = batch_ids (unused; graphs are contiguous)
    const float* W1  = (const float*)d_in[3];
    const float* as1 = (const float*)d_in[4];
    const float* ad1 = (const float*)d_in[5];
    const float* b1  = (const float*)d_in[6];
    const float* W2  = (const float*)d_in[7];
    const float* as2 = (const float*)d_in[8];
    const float* ad2 = (const float*)d_in[9];
    const float* b2  = (const float*)d_in[10];
    const float* W3  = (const float*)d_in[11];
    const float* as3 = (const float*)d_in[12];
    const float* ad3 = (const float*)d_in[13];
    const float* b3  = (const float*)d_in[14];
    const float* W4  = (const float*)d_in[15];
    const float* as4 = (const float*)d_in[16];
    const float* ad4 = (const float*)d_in[17];
    const float* b4  = (const float*)d_in[18];
    const float* lw1 = (const float*)d_in[19];
    const float* lb1 = (const float*)d_in[20];
    const float* lw2 = (const float*)d_in[21];
    const float* lb2 = (const float*)d_in[22];
    const float* lw3 = (const float*)d_in[23];
    const float* lb3 = (const float*)d_in[24];
    float* out = (float*)d_out;

    float *feat, *m1, *m2;
    cudaGetSymbolAddress((void**)&feat, g_feat);
    cudaGetSymbolAddress((void**)&m1, g_m1);
    cudaGetSymbolAddress((void**)&m2, g_m2);

    gat_kernel<<<NGRAPH, 256>>>(x, ei, W1, as1, ad1, b1, W2, as2, ad2, b2,
                                W3, as3, ad3, b3, W4, as4, ad4, b4, feat);

    // f [8192,4560] @ lw1 [4560,1024] -> relu -> m1
    gemm_bias_act<128, 128, 16, 8, 8, true>
        <<<dim3(1024 / 128, NGRAPH / 128), 256>>>(feat, lw1, lb1, m1,
                                                  NGRAPH, 1024, FDIM);
    // m1 [8192,1024] @ lw2 [1024,128] -> relu -> m2
    gemm_bias_act<64, 64, 16, 4, 4, true>
        <<<dim3(128 / 64, NGRAPH / 64), 256>>>(m1, lw2, lb2, m2,
                                               NGRAPH, 128, 1024);
    // m2 [8192,128] @ lw3 [128,9] + lb3 -> out
    gemm3_kernel<<<(NGRAPH * 9 + 255) / 256, 256>>>(m2, lw3, lb3, out);
}

// round 8
// speedup vs baseline: 1.3258x; 1.3258x over previous
#include <cuda_runtime.h>
#include <cuda_bf16.h>
#include <cstdint>

// ---------------- problem constants ----------------
#define NGRAPH 8192
#define NPG    39
#define EPG    312
#define NTOT   (NGRAPH * NPG)
#define ETOT   (NGRAPH * EPG)
#define FDIM   4560
#define KP     4608            // FDIM padded to 64
#define NEG_SLOPE 0.2f

#define OFF_RES0 0
#define OFF_RES1 39
#define OFF_RES2 351
#define OFF_RES3 2847
#define OFF_RES4 4095
#define OFF_OUT0 4446
#define OFF_OUT1 4447
#define OFF_OUT2 4455
#define OFF_OUT3 4519
#define OFF_OUT4 4551

// ---------------- scratch (device globals) ----------------
__device__ __nv_bfloat16 g_Ahi[(size_t)NGRAPH * KP];   // 75.5 MB
__device__ __nv_bfloat16 g_Alo[(size_t)NGRAPH * KP];   // 75.5 MB
__device__ __nv_bfloat16 g_Bhi[(size_t)1024 * KP];     // 9.4 MB
__device__ __nv_bfloat16 g_Blo[(size_t)1024 * KP];     // 9.4 MB
__device__ float g_m1[(size_t)NGRAPH * 1024];          // 33.5 MB
__device__ float g_m2[(size_t)NGRAPH * 128];           // 4.2 MB

// ---------------- generic helpers ----------------
__device__ __forceinline__ float lrelu(float v) { return v >= 0.f ? v : NEG_SLOPE * v; }
__device__ __forceinline__ unsigned encf(float f) {
    unsigned u = __float_as_uint(f);
    return (u & 0x80000000u) ? ~u : (u | 0x80000000u);
}
__device__ __forceinline__ float decf(unsigned u) {
    u = (u & 0x80000000u) ? (u & 0x7fffffffu) : ~u;
    return __uint_as_float(u);
}
__device__ __forceinline__ void store_hl(__nv_bfloat16* hi, __nv_bfloat16* lo,
                                         int idx, float v) {
    __nv_bfloat16 h = __float2bfloat16(v);
    hi[idx] = h;
    lo[idx] = __float2bfloat16(v - __bfloat162float(h));
}
__device__ __forceinline__ uint32_t smem_u32(const void* p) {
    uint32_t a;
    asm("{ .reg .u64 t; cvta.to.shared.u64 t, %1; cvt.u32.u64 %0, t; }" : "=r"(a) : "l"(p));
    return a;
}

// f32x2 packed FMA helpers (SIMT gemm2)
__device__ __forceinline__ unsigned long long pk2(float x, float y) {
    unsigned long long u;
    asm("mov.b64 %0, {%1, %2};" : "=l"(u) : "f"(x), "f"(y));
    return u;
}
__device__ __forceinline__ void upk2(unsigned long long u, float& x, float& y) {
    asm("mov.b64 {%0, %1}, %2;" : "=f"(x), "=f"(y) : "l"(u));
}
__device__ __forceinline__ void ffma2(unsigned long long& c, unsigned long long a,
                                      unsigned long long b) {
    asm("fma.rn.f32x2 %0, %1, %2, %0;" : "+l"(c) : "l"(a), "l"(b));
}

// ---------------- cp.async / ldmatrix / mma helpers (baseline PTX) --------
__device__ __forceinline__ void cp_async16(uint32_t dst, const void* src) {
    asm volatile("cp.async.cg.shared.global [%0], [%1], 16;" :: "r"(dst), "l"(src));
}
__device__ __forceinline__ void cp_commit() {
    asm volatile("cp.async.commit_group;" ::: "memory");
}
template <int N>
__device__ __forceinline__ void cp_wait_group() {
    asm volatile("cp.async.wait_group %0;" :: "n"(N) : "memory");
}
__device__ __forceinline__ void ldsm_x4(uint32_t* r, uint32_t addr) {
    asm volatile("ldmatrix.sync.aligned.m8n8.x4.shared.b16 {%0,%1,%2,%3}, [%4];"
                 : "=r"(r[0]), "=r"(r[1]), "=r"(r[2]), "=r"(r[3]) : "r"(addr));
}
__device__ __forceinline__ void mma16816(float* c, const uint32_t* a, const uint32_t* b) {
    asm volatile(
        "mma.sync.aligned.m16n8k16.row.col.f32.bf16.bf16.f32 "
        "{%0,%1,%2,%3}, {%4,%5,%6,%7}, {%8,%9}, {%0,%1,%2,%3};"
        : "+f"(c[0]), "+f"(c[1]), "+f"(c[2]), "+f"(c[3])
        : "r"(a[0]), "r"(a[1]), "r"(a[2]), "r"(a[3]), "r"(b[0]), "r"(b[1]));
}

// ---------------- GAT kernel: one CTA per graph ----------------
template <int Fi, int Fo>
__device__ void gat_layer_dev(
    float* __restrict__ xin, float* __restrict__ h, float* __restrict__ Wsh,
    float* __restrict__ sas, float* __restrict__ sad, float* __restrict__ sb,
    float* __restrict__ ss, float* __restrict__ sd, float* __restrict__ sden,
    unsigned* __restrict__ sm, float* __restrict__ sw,
    const short* __restrict__ es, const short* __restrict__ ed,
    const float* __restrict__ W, const float* __restrict__ a_s,
    const float* __restrict__ a_d, const float* __restrict__ bias,
    __nv_bfloat16* __restrict__ fhi, __nv_bfloat16* __restrict__ flo,
    int res_off, int pool_off)
{
    const int tid = threadIdx.x;
    for (int i = tid; i < Fi * Fo; i += 256) Wsh[i] = W[i];
    if (tid < Fo) { sas[tid] = a_s[tid]; sad[tid] = a_d[tid]; sb[tid] = bias[tid]; }
    __syncthreads();

    for (int idx = tid; idx < NPG * Fo; idx += 256) {
        int n = idx / Fo, f = idx - n * Fo;
        float acc = 0.f;
        #pragma unroll
        for (int i = 0; i < Fi; i++) acc += xin[n * Fi + i] * Wsh[i * Fo + f];
        h[idx] = acc;
    }
    __syncthreads();

    if (tid < NPG) {
        float a = 0.f, b = 0.f;
        #pragma unroll
        for (int f = 0; f < Fo; f++) {
            float hv = h[tid * Fo + f];
            a += hv * sas[f];
            b += hv * sad[f];
        }
        ss[tid] = a;
        sd[tid] = b;
        sm[tid] = encf(lrelu(a + b));
        sden[tid] = 0.f;
    }
    for (int idx = tid; idx < NPG * Fo; idx += 256) xin[idx] = 0.f;
    __syncthreads();

    for (int e = tid; e < EPG; e += 256) {
        float v = lrelu(ss[es[e]] + sd[ed[e]]);
        sw[e] = v;
        atomicMax(&sm[ed[e]], encf(v));
    }
    __syncthreads();

    if (tid < NPG) {
        float m = decf(sm[tid]);
        float wself = expf(lrelu(ss[tid] + sd[tid]) - m);
        atomicAdd(&sden[tid], wself);
        ss[tid] = wself;
    }
    for (int e = tid; e < EPG; e += 256) {
        float w = expf(sw[e] - decf(sm[ed[e]]));
        sw[e] = w;
        atomicAdd(&sden[ed[e]], w);
    }
    __syncthreads();

    for (int idx = tid; idx < EPG * Fo; idx += 256) {
        int e = idx / Fo, f = idx - e * Fo;
        atomicAdd(&xin[ed[e] * Fo + f], sw[e] * h[es[e] * Fo + f]);
    }
    for (int idx = tid; idx < NPG * Fo; idx += 256) {
        int n = idx / Fo;
        atomicAdd(&xin[idx], ss[n] * h[idx]);
    }
    __syncthreads();

    for (int idx = tid; idx < NPG * Fo; idx += 256) {
        int n = idx / Fo, f = idx - n * Fo;
        float o = xin[idx] / (sden[n] + 1e-16f) + sb[f];
        o = fmaxf(o, 0.f);
        xin[idx] = o;
        store_hl(fhi, flo, res_off + idx, o);
    }
    __syncthreads();

    for (int f = tid; f < Fo; f += 256) {
        float mx = -3.4e38f;
        #pragma unroll 1
        for (int n = 0; n < NPG; n++) mx = fmaxf(mx, xin[n * Fo + f]);
        store_hl(fhi, flo, pool_off + f, mx);
    }
    __syncthreads();
}

__global__ void __launch_bounds__(256)
gat_kernel(const float* __restrict__ x, const int* __restrict__ ei,
           const float* __restrict__ W1, const float* __restrict__ as1,
           const float* __restrict__ ad1, const float* __restrict__ b1,
           const float* __restrict__ W2, const float* __restrict__ as2,
           const float* __restrict__ ad2, const float* __restrict__ b2,
           const float* __restrict__ W3, const float* __restrict__ as3,
           const float* __restrict__ ad3, const float* __restrict__ b3,
           const float* __restrict__ W4, const float* __restrict__ as4,
           const float* __restrict__ ad4, const float* __restrict__ b4,
           __nv_bfloat16* __restrict__ Ahi, __nv_bfloat16* __restrict__ Alo)
{
    __shared__ float s_xin[NPG * 64];
    __shared__ float s_h[NPG * 64];
    __shared__ float s_W[64 * 32];
    __shared__ float s_as[64], s_ad[64], s_b[64];
    __shared__ float s_s[NPG], s_d[NPG], s_den[NPG];
    __shared__ unsigned s_m[NPG];
    __shared__ float s_w[EPG];
    __shared__ short s_es[EPG], s_ed[EPG];

    const int g = blockIdx.x;
    const int tid = threadIdx.x;
    __nv_bfloat16* fhi = Ahi + (size_t)g * KP;
    __nv_bfloat16* flo = Alo + (size_t)g * KP;

    const int ebase = g * EPG;
    const int nbase = g * NPG;
    for (int e = tid; e < EPG; e += 256) {
        s_es[e] = (short)(ei[ebase + e] - nbase);
        s_ed[e] = (short)(ei[ETOT + ebase + e] - nbase);
    }
    if (tid < NPG) {
        float xv = x[nbase + tid];
        s_xin[tid] = xv;
        store_hl(fhi, flo, OFF_RES0 + tid, xv);
    }
    if (tid < KP - FDIM) {
        fhi[FDIM + tid] = __float2bfloat16(0.f);
        flo[FDIM + tid] = __float2bfloat16(0.f);
    }
    __syncthreads();
    if (tid == 0) {
        float mx = -3.4e38f;
        for (int n = 0; n < NPG; n++) mx = fmaxf(mx, s_xin[n]);
        store_hl(fhi, flo, OFF_OUT0, mx);
    }

    gat_layer_dev<1, 8>(s_xin, s_h, s_W, s_as, s_ad, s_b, s_s, s_d, s_den, s_m,
                        s_w, s_es, s_ed, W1, as1, ad1, b1, fhi, flo, OFF_RES1, OFF_OUT1);
    gat_layer_dev<8, 64>(s_xin, s_h, s_W, s_as, s_ad, s_b, s_s, s_d, s_den, s_m,
                         s_w, s_es, s_ed, W2, as2, ad2, b2, fhi, flo, OFF_RES2, OFF_OUT2);
    gat_layer_dev<64, 32>(s_xin, s_h, s_W, s_as, s_ad, s_b, s_s, s_d, s_den, s_m,
                          s_w, s_es, s_ed, W3, as3, ad3, b3, fhi, flo, OFF_RES3, OFF_OUT3);
    gat_layer_dev<32, 9>(s_xin, s_h, s_W, s_as, s_ad, s_b, s_s, s_d, s_den, s_m,
                         s_w, s_es, s_ed, W4, as4, ad4, b4, fhi, flo, OFF_RES4, OFF_OUT4);
}

// ---------------- lw1 transpose + bf16 split: [4560,1024] -> [1024,4608] ---
__global__ void __launch_bounds__(256)
convB_kernel(const float* __restrict__ lw1,
             __nv_bfloat16* __restrict__ Bhi, __nv_bfloat16* __restrict__ Blo)
{
    __shared__ float t[32][33];
    const int k0 = blockIdx.x * 32;
    const int n0 = blockIdx.y * 32;
    const int tx = threadIdx.x & 31;
    const int ty = threadIdx.x >> 5;  // 0..7
    #pragma unroll
    for (int j = 0; j < 4; j++) {
        int k = k0 + ty + j * 8;
        t[ty + j * 8][tx] = (k < FDIM) ? lw1[(size_t)k * 1024 + (n0 + tx)] : 0.f;
    }
    __syncthreads();
    #pragma unroll
    for (int j = 0; j < 4; j++) {
        int n = n0 + ty + j * 8;
        int k = k0 + tx;
        float v = t[tx][ty + j * 8];
        __nv_bfloat16 h = __float2bfloat16(v);
        Bhi[(size_t)n * KP + k] = h;
        Blo[(size_t)n * KP + k] = __float2bfloat16(v - __bfloat162float(h));
    }
}

// ---------------- GEMM1: mma.sync bf16x3, M=8192, N=1024, K=4608 -----------
// Tiles: BM=128, BN=128, BK=32, 3-stage cp.async pipeline.
// smem rows: 32 bf16 = 64B data at 80B pitch -> conflict-free ldmatrix.
#define G1_BK      32
#define G1_PITCH   80
#define G1_ARR     (128 * G1_PITCH)          // 10240 B per array
#define G1_STAGE   (4 * G1_ARR)              // 40960 B
#define G1_STAGES  3
#define G1_SMEM    (G1_STAGES * G1_STAGE)    // 122880 B
#define G1_CHUNKS  (KP / G1_BK)              // 144

__device__ __forceinline__ void g1_load(
    uint32_t st, int k0, int row0, int col0, int tid,
    const __nv_bfloat16* __restrict__ Ahi, const __nv_bfloat16* __restrict__ Alo,
    const __nv_bfloat16* __restrict__ Bhi, const __nv_bfloat16* __restrict__ Blo)
{
    #pragma unroll
    for (int j = 0; j < 2; j++) {
        int s = tid + j * 256;               // 0..511
        int row = s >> 2, ch = s & 3;
        uint32_t dst = st + (uint32_t)(row * G1_PITCH + ch * 16);
        size_t goffA = (size_t)(row0 + row) * KP + k0 + ch * 8;
        size_t goffB = (size_t)(col0 + row) * KP + k0 + ch * 8;
        cp_async16(dst,               Ahi + goffA);
        cp_async16(dst + G1_ARR,      Alo + goffA);
        cp_async16(dst + 2 * G1_ARR,  Bhi + goffB);
        cp_async16(dst + 3 * G1_ARR,  Blo + goffB);
    }
}

__global__ void __launch_bounds__(256)
gemm1_mma(const __nv_bfloat16* __restrict__ Ahi, const __nv_bfloat16* __restrict__ Alo,
          const __nv_bfloat16* __restrict__ Bhi, const __nv_bfloat16* __restrict__ Blo,
          const float* __restrict__ bias, float* __restrict__ C)
{
    extern __shared__ char dsm_raw[];
    const uint32_t dsm = smem_u32(dsm_raw);

    const int tid = threadIdx.x;
    const int wid = tid >> 5, lid = tid & 31;
    const int wm = wid & 1;          // 2 warps along M (64 each)
    const int wn = wid >> 1;         // 4 warps along N (32 each)
    const int row0 = blockIdx.y * 128;
    const int col0 = blockIdx.x * 128;

    float acc[4][4][4];
    #pragma unroll
    for (int i = 0; i < 4; i++)
        #pragma unroll
        for (int j = 0; j < 4; j++)
            #pragma unroll
            for (int k = 0; k < 4; k++) acc[i][j][k] = 0.f;

    // prologue
    #pragma unroll
    for (int s = 0; s < G1_STAGES - 1; s++) {
        g1_load(dsm + s * G1_STAGE, s * G1_BK, row0, col0, tid, Ahi, Alo, Bhi, Blo);
        cp_commit();
    }

    const int lr = lid & 7, g = lid >> 3;
    // base offsets (add mf/nf2 * 1280 and ks * 32)
    const uint32_t aoff = (uint32_t)((wm * 64 + lr + ((g & 1) << 3)) * G1_PITCH
                                     + ((g >> 1) << 4));
    const uint32_t boff = (uint32_t)((wn * 32 + lr + (((g >> 1) & 1) << 3)) * G1_PITCH
                                     + ((g & 1) << 4));

    for (int i = 0; i < G1_CHUNKS; i++) {
        cp_wait_group<G1_STAGES - 2>();
        __syncthreads();

        // prefetch stage i + STAGES-1
        int c = i + G1_STAGES - 1;
        if (c < G1_CHUNKS)
            g1_load(dsm + (c % G1_STAGES) * G1_STAGE, c * G1_BK, row0, col0, tid,
                    Ahi, Alo, Bhi, Blo);
        cp_commit();

        const uint32_t sA  = dsm + (i % G1_STAGES) * G1_STAGE;
        const uint32_t sAl = sA + G1_ARR;
        const uint32_t sB  = sA + 2 * G1_ARR;
        const uint32_t sBl = sA + 3 * G1_ARR;

        #pragma unroll
        for (int ks = 0; ks < 2; ks++) {
            uint32_t ah[4][4], al[4][4], bh[2][4], bl[2][4];
            #pragma unroll
            for (int mf = 0; mf < 4; mf++) {
                ldsm_x4(ah[mf], sA  + aoff + mf * (16 * G1_PITCH) + ks * 32);
                ldsm_x4(al[mf], sAl + aoff + mf * (16 * G1_PITCH) + ks * 32);
            }
            #pragma unroll
            for (int nf2 = 0; nf2 < 2; nf2++) {
                ldsm_x4(bh[nf2], sB  + boff + nf2 * (16 * G1_PITCH) + ks * 32);
                ldsm_x4(bl[nf2], sBl + boff + nf2 * (16 * G1_PITCH) + ks * 32);
            }
            #pragma unroll
            for (int mf = 0; mf < 4; mf++) {
                #pragma unroll
                for (int nf = 0; nf < 4; nf++) {
                    const uint32_t* fh = &bh[nf >> 1][(nf & 1) * 2];
                    const uint32_t* fl = &bl[nf >> 1][(nf & 1) * 2];
                    mma16816(acc[mf][nf], ah[mf], fh);
                    mma16816(acc[mf][nf], ah[mf], fl);
                    mma16816(acc[mf][nf], al[mf], fh);
                }
            }
        }
    }

    // epilogue: bias + relu + store
    const int mbase = row0 + wm * 64 + (lid >> 2);
    const int nbase = col0 + wn * 32 + (lid & 3) * 2;
    #pragma unroll
    for (int mf = 0; mf < 4; mf++) {
        #pragma unroll
        for (int nf = 0; nf < 4; nf++) {
            int r0 = mbase + mf * 16;
            int cc = nbase + nf * 8;
            float b0 = bias[cc], b1 = bias[cc + 1];
            float v0 = fmaxf(acc[mf][nf][0] + b0, 0.f);
            float v1 = fmaxf(acc[mf][nf][1] + b1, 0.f);
            float v2 = fmaxf(acc[mf][nf][2] + b0, 0.f);
            float v3 = fmaxf(acc[mf][nf][3] + b1, 0.f);
            C[(size_t)r0 * 1024 + cc]       = v0;
            C[(size_t)r0 * 1024 + cc + 1]   = v1;
            C[(size_t)(r0 + 8) * 1024 + cc]     = v2;
            C[(size_t)(r0 + 8) * 1024 + cc + 1] = v3;
        }
    }
}

// ---------------- GEMM2 SIMT (+bias+relu) ----------------
template <int BM, int BN, int BK, int TM, int TN, bool RELU>
__global__ void __launch_bounds__((BM / TM) * (BN / TN))
gemm_bias_act(const float* __restrict__ A, const float* __restrict__ Bm,
              const float* __restrict__ bias, float* __restrict__ C,
              int M, int N, int K)
{
    constexpr int THREADS = (BM / TM) * (BN / TN);
    constexpr int NT = BN / TN;
    __shared__ float As[BK][BM];
    __shared__ float Bs[BK][BN];
    const int tid = threadIdx.x;
    const int row0 = blockIdx.y * BM;
    const int col0 = blockIdx.x * BN;
    const int tr = tid / NT;
    const int tc = tid % NT;

    unsigned long long acc[TM][TN / 2];
    #pragma unroll
    for (int i = 0; i < TM; i++)
        #pragma unroll
        for (int j = 0; j < TN / 2; j++) acc[i][j] = 0ull;

    constexpr int AV = BM * BK / (4 * THREADS);
    constexpr int BV = BK * BN / (4 * THREADS);

    for (int k0 = 0; k0 < K; k0 += BK) {
        #pragma unroll
        for (int v = 0; v < AV; v++) {
            int e = (tid + v * THREADS) * 4;
            int r = e / BK, kk = e % BK;
            float4 t = *(const float4*)(A + (size_t)(row0 + r) * K + (k0 + kk));
            As[kk + 0][r] = t.x; As[kk + 1][r] = t.y;
            As[kk + 2][r] = t.z; As[kk + 3][r] = t.w;
        }
        #pragma unroll
        for (int v = 0; v < BV; v++) {
            int e = (tid + v * THREADS) * 4;
            int kk = e / BN, c = e % BN;
            *(float4*)&Bs[kk][c] = *(const float4*)(Bm + (size_t)(k0 + kk) * N + (col0 + c));
        }
        __syncthreads();

        #pragma unroll
        for (int kk = 0; kk < BK; kk++) {
            float a[TM], b[TN];
            float4 a0 = *(const float4*)&As[kk][tr * 4];
            a[0] = a0.x; a[1] = a0.y; a[2] = a0.z; a[3] = a0.w;
            float4 b0 = *(const float4*)&Bs[kk][tc * 4];
            b[0] = b0.x; b[1] = b0.y; b[2] = b0.z; b[3] = b0.w;
            unsigned long long bb[TN / 2];
            #pragma unroll
            for (int j = 0; j < TN / 2; j++) bb[j] = pk2(b[2 * j], b[2 * j + 1]);
            #pragma unroll
            for (int i = 0; i < TM; i++) {
                unsigned long long ai = pk2(a[i], a[i]);
                #pragma unroll
                for (int j = 0; j < TN / 2; j++) ffma2(acc[i][j], ai, bb[j]);
            }
        }
        __syncthreads();
    }

    #pragma unroll
    for (int i = 0; i < TM; i++) {
        int row = row0 + tr * 4 + i;
        #pragma unroll
        for (int j = 0; j < TN / 2; j++) {
            float v0, v1;
            upk2(acc[i][j], v0, v1);
            int col = col0 + tc * 4 + 2 * j;
            v0 += bias[col];
            v1 += bias[col + 1];
            if (RELU) { v0 = fmaxf(v0, 0.f); v1 = fmaxf(v1, 0.f); }
            C[(size_t)row * N + col] = v0;
            C[(size_t)row * N + col + 1] = v1;
        }
    }
}

// ---------------- final tiny GEMM ----------------
__global__ void gemm3_kernel(const float* __restrict__ A, const float* __restrict__ W,
                             const float* __restrict__ bias, float* __restrict__ C)
{
    int idx = blockIdx.x * blockDim.x + threadIdx.x;
    if (idx >= NGRAPH * 9) return;
    int m = idx / 9, n = idx - m * 9;
    const float* a = A + (size_t)m * 128;
    float acc = 0.f;
    #pragma unroll 8
    for (int k = 0; k < 128; k++) acc += a[k] * W[k * 9 + n];
    C[idx] = acc + bias[n];
}

// ---------------- launch ----------------
extern "C" void kernel_launch(void* const* d_in, const int* in_sizes, int n_in,
                              void* d_out, int out_size)
{
    (void)in_sizes; (void)n_in; (void)out_size;
    const float* x   = (const float*)d_in[0];
    const int*   ei  = (const int*)d_in[1];
    const float* W1  = (const float*)d_in[3];
    const float* as1 = (const float*)d_in[4];
    const float* ad1 = (const float*)d_in[5];
    const float* b1  = (const float*)d_in[6];
    const float* W2  = (const float*)d_in[7];
    const float* as2 = (const float*)d_in[8];
    const float* ad2 = (const float*)d_in[9];
    const float* b2  = (const float*)d_in[10];
    const float* W3  = (const float*)d_in[11];
    const float* as3 = (const float*)d_in[12];
    const float* ad3 = (const float*)d_in[13];
    const float* b3  = (const float*)d_in[14];
    const float* W4  = (const float*)d_in[15];
    const float* as4 = (const float*)d_in[16];
    const float* ad4 = (const float*)d_in[17];
    const float* b4  = (const float*)d_in[18];
    const float* lw1 = (const float*)d_in[19];
    const float* lb1 = (const float*)d_in[20];
    const float* lw2 = (const float*)d_in[21];
    const float* lb2 = (const float*)d_in[22];
    const float* lw3 = (const float*)d_in[23];
    const float* lb3 = (const float*)d_in[24];
    float* out = (float*)d_out;

    __nv_bfloat16 *Ahi, *Alo, *Bhi, *Blo;
    float *m1, *m2;
    cudaGetSymbolAddress((void**)&Ahi, g_Ahi);
    cudaGetSymbolAddress((void**)&Alo, g_Alo);
    cudaGetSymbolAddress((void**)&Bhi, g_Bhi);
    cudaGetSymbolAddress((void**)&Blo, g_Blo);
    cudaGetSymbolAddress((void**)&m1, g_m1);
    cudaGetSymbolAddress((void**)&m2, g_m2);

    cudaFuncSetAttribute(gemm1_mma, cudaFuncAttributeMaxDynamicSharedMemorySize,
                         G1_SMEM);

    convB_kernel<<<dim3(KP / 32, 1024 / 32), 256>>>(lw1, Bhi, Blo);
    gat_kernel<<<NGRAPH, 256>>>(x, ei, W1, as1, ad1, b1, W2, as2, ad2, b2,
                                W3, as3, ad3, b3, W4, as4, ad4, b4, Ahi, Alo);

    gemm1_mma<<<dim3(1024 / 128, NGRAPH / 128), 256, G1_SMEM>>>(
        Ahi, Alo, Bhi, Blo, lb1, m1);

    gemm_bias_act<64, 64, 16, 4, 4, true>
        <<<dim3(128 / 64, NGRAPH / 64), 256>>>(m1, lw2, lb2, m2, NGRAPH, 128, 1024);
    gemm3_kernel<<<(NGRAPH * 9 + 255) / 256, 256>>>(m2, lw3, lb3, out);
}